// round 15
// baseline (speedup 1.0000x reference)
#include <cuda_runtime.h>
#include <cuda_fp16.h>
#include <math.h>
#include <stdint.h>

#define TOKENS 8192
#define DM 1024
#define DF 2048
#define NE 8

// ---------------- scratch (device globals: allocation-free, graph-safe) -------------
__device__ int    g_cnt[2];
__device__ int    g_idx[2][TOKENS];
__device__ float  g_scale[2][TOKENS];
__device__ __half g_xa[2][(size_t)TOKENS * DM];   // compacted fp16 x rows
__device__ __half g_hh[2][(size_t)TOKENS * DF];   // fp16 h rows (scale folded)
__device__ __half g_w1t[2][(size_t)DM * DF];      // w1 transposed: [n=2048][k=1024]
__device__ __half g_w2t[2][(size_t)DF * DM];      // w2 transposed: [n=1024][k=2048]

__global__ void reset_kernel() {
    if (threadIdx.x < 2) g_cnt[threadIdx.x] = 0;
}

// Convert + transpose weights of experts 0,1 to fp16 n-major.
__global__ __launch_bounds__(256) void prep_w_kernel(const float* __restrict__ w1,
                                                     const float* __restrict__ w2) {
    const int z = blockIdx.z;
    const float* src;
    __half* dst;
    int K, N;
    if (z < 2) { src = w1 + (size_t)z * DM * DF; dst = g_w1t[z]; K = DM; N = DF; }
    else       { src = w2 + (size_t)(z - 2) * DF * DM; dst = g_w2t[z - 2]; K = DF; N = DM; }
    const int k0 = blockIdx.x * 32, n0 = blockIdx.y * 32;
    if (k0 >= K || n0 >= N) return;

    __shared__ float s[32][33];
    const int tx = threadIdx.x, ty = threadIdx.y;   // 32 x 8
#pragma unroll
    for (int i = 0; i < 4; i++)
        s[ty + 8 * i][tx] = src[(size_t)(k0 + ty + 8 * i) * N + n0 + tx];
    __syncthreads();
#pragma unroll
    for (int i = 0; i < 4; i++)
        dst[(size_t)(n0 + ty + 8 * i) * K + k0 + tx] = __float2half(s[tx][ty + 8 * i]);
}

// One warp per token: gate + top-2 + compaction + fused fp16 x-row scatter.
__global__ __launch_bounds__(256) void gate_kernel(const float* __restrict__ x,
                                                   const float* __restrict__ gw,
                                                   const float* __restrict__ gb) {
    __shared__ float sgwT[NE][DM];
    for (int i = threadIdx.x; i < DM * NE; i += 256) {
        int d = i >> 3, e = i & 7;   // gw is [d][e] row-major
        sgwT[e][d] = gw[i];
    }
    __syncthreads();

    const int t    = (int)((blockIdx.x * 256u + threadIdx.x) >> 5);
    const int lane = threadIdx.x & 31;
    if (t >= TOKENS) return;

    const float* xr = x + (size_t)t * DM;
    float acc[NE];
#pragma unroll
    for (int e = 0; e < NE; e++) acc[e] = 0.f;
    for (int d = lane; d < DM; d += 32) {
        const float xv = xr[d];
#pragma unroll
        for (int e = 0; e < NE; e++) acc[e] += xv * sgwT[e][d];
    }
#pragma unroll
    for (int e = 0; e < NE; e++)
#pragma unroll
        for (int o = 16; o > 0; o >>= 1) acc[e] += __shfl_xor_sync(0xffffffffu, acc[e], o);

    int s0v = -1, s1v = -1;
    if (lane == 0) {
        float p[NE];
        float mx = -1e30f;
#pragma unroll
        for (int e = 0; e < NE; e++) { p[e] = acc[e] + gb[e]; mx = fmaxf(mx, p[e]); }
        float s = 0.f;
#pragma unroll
        for (int e = 0; e < NE; e++) { p[e] = expf(p[e] - mx); s += p[e]; }
        float inv = 1.f / s;
#pragma unroll
        for (int e = 0; e < NE; e++) p[e] *= inv;
        int i1 = 0;
#pragma unroll
        for (int e = 1; e < NE; e++) if (p[e] > p[i1]) i1 = e;
        int i2 = (i1 == 0) ? 1 : 0;
#pragma unroll
        for (int e = 0; e < NE; e++) if (e != i1 && p[e] > p[i2]) i2 = e;
        if (i1 == 0) { s0v = atomicAdd(&g_cnt[0], 1); g_idx[0][s0v] = t; g_scale[0][s0v] = p[0]; }
        if (i2 == 1) { s1v = atomicAdd(&g_cnt[1], 1); g_idx[1][s1v] = t; g_scale[1][s1v] = p[1]; }
    }
    const int slot0 = __shfl_sync(0xffffffffu, s0v, 0);
    const int slot1 = __shfl_sync(0xffffffffu, s1v, 0);
    if (slot0 < 0 && slot1 < 0) return;

    // warp-wide fp16 conversion of the (cache-hot) x row, scattered to slots
    const float4* src4 = (const float4*)xr;
    for (int j = lane; j < DM / 8; j += 32) {
        float4 v0 = src4[2 * j], v1 = src4[2 * j + 1];
        __half2 h0 = __floats2half2_rn(v0.x, v0.y);
        __half2 h1 = __floats2half2_rn(v0.z, v0.w);
        __half2 h2 = __floats2half2_rn(v1.x, v1.y);
        __half2 h3 = __floats2half2_rn(v1.z, v1.w);
        uint4 u;
        u.x = *(uint32_t*)&h0; u.y = *(uint32_t*)&h1;
        u.z = *(uint32_t*)&h2; u.w = *(uint32_t*)&h3;
        if (slot0 >= 0) ((uint4*)(g_xa[0] + (size_t)slot0 * DM))[j] = u;
        if (slot1 >= 0) ((uint4*)(g_xa[1] + (size_t)slot1 * DM))[j] = u;
    }
}

// ---------------- fp16 mma.sync GEMM with cp.async pipeline ----------------
__device__ __forceinline__ void mma_f16(float* d, const uint32_t* a, const uint32_t* b) {
    asm volatile(
        "mma.sync.aligned.m16n8k16.row.col.f32.f16.f16.f32 "
        "{%0,%1,%2,%3}, {%4,%5,%6,%7}, {%8,%9}, {%0,%1,%2,%3};"
        : "+f"(d[0]), "+f"(d[1]), "+f"(d[2]), "+f"(d[3])
        : "r"(a[0]), "r"(a[1]), "r"(a[2]), "r"(a[3]), "r"(b[0]), "r"(b[1]));
}
__device__ __forceinline__ uint32_t smem_u32(const void* p) {
    uint32_t a;
    asm("{ .reg .u64 t; cvta.to.shared.u64 t, %1; cvt.u32.u64 %0, t; }" : "=r"(a) : "l"(p));
    return a;
}
#define CP_ASYNC16(dst, src) \
    asm volatile("cp.async.cg.shared.global [%0], [%1], 16;" :: "r"(dst), "l"(src))
#define CP_ASYNC16Z(dst, src, sz) \
    asm volatile("cp.async.cg.shared.global [%0], [%1], 16, %2;" \
                 :: "r"(dst), "l"(src), "r"(sz))
#define CP_COMMIT() asm volatile("cp.async.commit_group;" ::: "memory")
#define CP_WAIT1()  asm volatile("cp.async.wait_group 1;" ::: "memory")
#define REDV2(ptr, v0, v1) \
    asm volatile("red.global.add.v2.f32 [%0], {%1, %2};" \
                 :: "l"(ptr), "f"(v0), "f"(v1) : "memory")

// CTA tile 128x128, BK=64 (fp16), 4 warps as 2(M) x 2(N); warp tile 64x64. 128 threads.
#define BM 128
#define BN 128
#define BK 64
#define AH_STRIDE 72                       // halves per smem row (64 data + 8 pad)
#define ROW_BYTES (AH_STRIDE * 2)          // 144
#define B_OFF_H (BM * AH_STRIDE)           // 9216 halves
#define STAGE_HALVES (2 * BM * AH_STRIDE)  // 18432
#define STAGE_BYTES (STAGE_HALVES * 2)     // 36864
#define STAGES 3
#define SMEM_TOTAL (STAGES * STAGE_BYTES)  // 110592 (2 CTA/SM: 221184 <= 227KB)

#define LD32H(base, idx) (*(const uint32_t*)((base) + (idx)))

template <int KTOT, int KSLICE, bool IS_FFN1, int SPLITK>
__global__ void __launch_bounds__(128, 2) ffn_f16_kernel(const float* __restrict__ bias,
                                                         float* __restrict__ outp) {
    const int e     = blockIdx.z / SPLITK;
    const int split = blockIdx.z % SPLITK;
    const int n_act = g_cnt[e];
    const int m0    = blockIdx.y * BM;
    if (m0 >= n_act) return;
    const int NOUT  = IS_FFN1 ? DF : DM;
    const int n0    = blockIdx.x * BN;
    const int kbase = split * KSLICE;
    const __half* __restrict__ Ae = IS_FFN1 ? g_xa[e] : g_hh[e];
    const __half* __restrict__ Wt = IS_FFN1 ? g_w1t[e] : g_w2t[e];

    extern __shared__ __half dynsmem_h[];

    const int tid  = threadIdx.x;
    const int wid  = tid >> 5;
    const int lane = tid & 31;
    const int gid  = lane >> 2;
    const int tig  = lane & 3;
    const int wm0  = (wid >> 1) * 64;   // 0 / 64
    const int wn0  = (wid & 1) * 64;    // 0 / 64

    // A: thread t covers row m0+t; invalid rows zero-filled via cp.async src-size=0.
    const bool arow_ok = (m0 + tid) < n_act;
    const uint32_t a_sz = arow_ok ? 16u : 0u;
    const __half* aptr = Ae + (size_t)(arow_ok ? (m0 + tid) : 0) * KTOT + kbase;
    // B: thread t loads Wt row n0+t (64 halves)
    const __half* bptr = Wt + (size_t)(n0 + tid) * KTOT + kbase;

    const uint32_t as_dst = smem_u32(dynsmem_h) + (uint32_t)(tid * ROW_BYTES);
    const uint32_t bs_dst = as_dst + (uint32_t)(B_OFF_H * 2);

    const int NCHUNK = KSLICE / BK;

    auto issue = [&](int chunk) {
        if (chunk < NCHUNK) {
            const uint32_t sb = (uint32_t)((chunk % STAGES) * STAGE_BYTES);
            const __half* ap = aptr + chunk * BK;
            const __half* bp = bptr + chunk * BK;
#pragma unroll
            for (int i = 0; i < 8; i++) CP_ASYNC16Z(as_dst + sb + i * 16, ap + i * 8, a_sz);
#pragma unroll
            for (int i = 0; i < 8; i++) CP_ASYNC16(bs_dst + sb + i * 16, bp + i * 8);
        }
        CP_COMMIT();   // uniform groups: wait_group(1) always pins chunk i
    };

    float c[4][8][4];
#pragma unroll
    for (int mi = 0; mi < 4; mi++)
#pragma unroll
        for (int ni = 0; ni < 8; ni++)
#pragma unroll
            for (int q = 0; q < 4; q++) c[mi][ni][q] = 0.f;

    uint32_t a[2][4][4], b[2][8][2];

#define LOAD_FRAGS(buf, ks_)                                                  \
    do {                                                                      \
        const int kk = (ks_) * 16;                                            \
        _Pragma("unroll")                                                     \
        for (int mi = 0; mi < 4; mi++) {                                      \
            const int r = wm0 + mi * 16 + gid;                                \
            a[buf][mi][0] = LD32H(As, r * AH_STRIDE + kk + 2 * tig);          \
            a[buf][mi][1] = LD32H(As, (r + 8) * AH_STRIDE + kk + 2 * tig);    \
            a[buf][mi][2] = LD32H(As, r * AH_STRIDE + kk + 2 * tig + 8);      \
            a[buf][mi][3] = LD32H(As, (r + 8) * AH_STRIDE + kk + 2 * tig + 8);\
        }                                                                     \
        _Pragma("unroll")                                                     \
        for (int ni = 0; ni < 8; ni++) {                                      \
            const int nn = wn0 + ni * 8 + gid;                                \
            b[buf][ni][0] = LD32H(Bs, nn * AH_STRIDE + kk + 2 * tig);         \
            b[buf][ni][1] = LD32H(Bs, nn * AH_STRIDE + kk + 2 * tig + 8);     \
        }                                                                     \
    } while (0)

    issue(0);
    issue(1);

    for (int i = 0; i < NCHUNK; i++) {
        CP_WAIT1();
        __syncthreads();
        // single sync is safe: issue writes stage (i+2)%3, compute reads i%3,
        // and the overwritten stage (i-1)%3 was released by this barrier.
        issue(i + 2);

        const __half* As = dynsmem_h + (i % STAGES) * STAGE_HALVES;
        const __half* Bs = As + B_OFF_H;

        LOAD_FRAGS(0, 0);
#pragma unroll
        for (int ks = 0; ks < 4; ks++) {
            if (ks < 3) LOAD_FRAGS((ks + 1) & 1, ks + 1);
            const int cb = ks & 1;
#pragma unroll
            for (int mi = 0; mi < 4; mi++)
#pragma unroll
                for (int ni = 0; ni < 8; ni++) mma_f16(c[mi][ni], a[cb][mi], b[cb][ni]);
        }
    }
#undef LOAD_FRAGS

    // ---------------- epilogue ----------------
    const float* bb = bias + (size_t)e * NOUT + n0;
    if (IS_FFN1) {
#pragma unroll
        for (int mi = 0; mi < 4; mi++) {
#pragma unroll
            for (int half_ = 0; half_ < 2; half_++) {
                const int r = m0 + wm0 + mi * 16 + gid + half_ * 8;
                if (r < n_act) {
                    const float sc = g_scale[e][r];          // fold scale into h
                    __half* hrow = g_hh[e] + (size_t)r * DF + n0;
#pragma unroll
                    for (int ni = 0; ni < 8; ni++) {
                        const int nn = wn0 + ni * 8 + 2 * tig;
                        float v0 = c[mi][ni][2 * half_ + 0] + bb[nn];
                        float v1 = c[mi][ni][2 * half_ + 1] + bb[nn + 1];
                        float o0 = sc * (0.5f * v0 * (1.f + erff(v0 * 0.70710678118654752f)));
                        float o1 = sc * (0.5f * v1 * (1.f + erff(v1 * 0.70710678118654752f)));
                        *(__half2*)(hrow + nn) = __floats2half2_rn(o0, o1);
                    }
                }
            }
        }
    } else {
#pragma unroll
        for (int mi = 0; mi < 4; mi++) {
#pragma unroll
            for (int half_ = 0; half_ < 2; half_++) {
                const int r = m0 + wm0 + mi * 16 + gid + half_ * 8;
                if (r < n_act) {
                    const int   tok = g_idx[e][r];
                    const float sc  = g_scale[e][r];
                    float* orow = outp + (size_t)tok * DM + n0;
#pragma unroll
                    for (int ni = 0; ni < 8; ni++) {
                        const int nn = wn0 + ni * 8 + 2 * tig;
                        // h already carries sc; bias needs sc, added by split 0 only
                        float bb0 = (split == 0) ? sc * bb[nn]     : 0.f;
                        float bb1 = (split == 0) ? sc * bb[nn + 1] : 0.f;
                        REDV2(orow + nn, c[mi][ni][2 * half_ + 0] + bb0,
                                         c[mi][ni][2 * half_ + 1] + bb1);
                    }
                }
            }
        }
    }
}

extern "C" void kernel_launch(void* const* d_in, const int* in_sizes, int n_in,
                              void* d_out, int out_size) {
    const float* x  = (const float*)d_in[0];
    const float* gw = (const float*)d_in[1];
    const float* gb = (const float*)d_in[2];
    const float* w1 = (const float*)d_in[3];
    const float* b1 = (const float*)d_in[4];
    const float* w2 = (const float*)d_in[5];
    const float* b2 = (const float*)d_in[6];
    float* out = (float*)d_out;

    cudaFuncSetAttribute(ffn_f16_kernel<DM, DM, true, 1>,
                         cudaFuncAttributeMaxDynamicSharedMemorySize, SMEM_TOTAL);
    cudaFuncSetAttribute(ffn_f16_kernel<DF, DF / 2, false, 2>,
                         cudaFuncAttributeMaxDynamicSharedMemorySize, SMEM_TOTAL);

    cudaMemsetAsync(out, 0, (size_t)out_size * sizeof(float), 0);
    reset_kernel<<<1, 32>>>();
    prep_w_kernel<<<dim3(64, 64, 4), dim3(32, 8)>>>(w1, w2);
    gate_kernel<<<TOKENS / 8, 256>>>(x, gw, gb);   // fused compaction + fp16 scatter
    // ffn1: active CTAs ~ 16x8x2 = 256 -> single wave at 2 CTA/SM
    ffn_f16_kernel<DM, DM, true, 1>
        <<<dim3(DF / BN, TOKENS / BM, 2), 128, SMEM_TOTAL>>>(b1, nullptr);
    // ffn2: split-K=2; active CTAs ~ 8x8x4 = 256 -> single wave at 2 CTA/SM
    ffn_f16_kernel<DF, DF / 2, false, 2>
        <<<dim3(DM / BN, TOKENS / BM, 4), 128, SMEM_TOTAL>>>(b2, out);
}

// round 16
// speedup vs baseline: 1.0740x; 1.0740x over previous
#include <cuda_runtime.h>
#include <cuda_fp16.h>
#include <math.h>
#include <stdint.h>

#define TOKENS 8192
#define DM 1024
#define DF 2048
#define NE 8

// ---------------- scratch (device globals: allocation-free, graph-safe) -------------
// g_cnt is statically zero-initialized; cleanup_kernel restores 0 after every call.
__device__ int    g_cnt[2];
__device__ int    g_idx[2][TOKENS];
__device__ float  g_scale[2][TOKENS];
__device__ __half g_xa[2][(size_t)TOKENS * DM];   // compacted fp16 x rows
__device__ __half g_hh[2][(size_t)TOKENS * DF];   // fp16 h rows (scale folded)
__device__ __half g_w1t[2][(size_t)DM * DF];      // w1 transposed: [n=2048][k=1024]
__device__ __half g_w2t[2][(size_t)DF * DM];      // w2 transposed: [n=1024][k=2048]

#define GATE_BLKS 1024
#define PREP_BLKS 8192   // 4 mats x 2048 tight 32x32 tiles

// One fused prologue: gate+compact+fp16-scatter | weight transpose/convert | zero out.
__global__ __launch_bounds__(256) void prologue_kernel(const float* __restrict__ x,
                                                       const float* __restrict__ gw,
                                                       const float* __restrict__ gb,
                                                       const float* __restrict__ w1,
                                                       const float* __restrict__ w2,
                                                       float* __restrict__ out,
                                                       int out_size) {
    const int bid = blockIdx.x;
    const int tid = threadIdx.x;

    if (bid < GATE_BLKS) {
        // ---------------- gate branch (8 warps -> 8 tokens) ----------------
        __shared__ float sgwT[NE][DM];
        for (int i = tid; i < DM * NE; i += 256) {
            int d = i >> 3, e = i & 7;   // gw is [d][e] row-major
            sgwT[e][d] = gw[i];
        }
        __syncthreads();

        const int t    = bid * 8 + (tid >> 5);
        const int lane = tid & 31;

        const float* xr = x + (size_t)t * DM;
        float acc[NE];
#pragma unroll
        for (int e = 0; e < NE; e++) acc[e] = 0.f;
        for (int d = lane; d < DM; d += 32) {
            const float xv = xr[d];
#pragma unroll
            for (int e = 0; e < NE; e++) acc[e] += xv * sgwT[e][d];
        }
#pragma unroll
        for (int e = 0; e < NE; e++)
#pragma unroll
            for (int o = 16; o > 0; o >>= 1) acc[e] += __shfl_xor_sync(0xffffffffu, acc[e], o);

        int s0v = -1, s1v = -1;
        if (lane == 0) {
            float p[NE];
            float mx = -1e30f;
#pragma unroll
            for (int e = 0; e < NE; e++) { p[e] = acc[e] + gb[e]; mx = fmaxf(mx, p[e]); }
            float s = 0.f;
#pragma unroll
            for (int e = 0; e < NE; e++) { p[e] = expf(p[e] - mx); s += p[e]; }
            float inv = 1.f / s;
#pragma unroll
            for (int e = 0; e < NE; e++) p[e] *= inv;
            int i1 = 0;
#pragma unroll
            for (int e = 1; e < NE; e++) if (p[e] > p[i1]) i1 = e;
            int i2 = (i1 == 0) ? 1 : 0;
#pragma unroll
            for (int e = 0; e < NE; e++) if (e != i1 && p[e] > p[i2]) i2 = e;
            if (i1 == 0) { s0v = atomicAdd(&g_cnt[0], 1); g_idx[0][s0v] = t; g_scale[0][s0v] = p[0]; }
            if (i2 == 1) { s1v = atomicAdd(&g_cnt[1], 1); g_idx[1][s1v] = t; g_scale[1][s1v] = p[1]; }
        }
        const int slot0 = __shfl_sync(0xffffffffu, s0v, 0);
        const int slot1 = __shfl_sync(0xffffffffu, s1v, 0);
        if (slot0 < 0 && slot1 < 0) return;

        const float4* src4 = (const float4*)xr;
        for (int j = lane; j < DM / 8; j += 32) {
            float4 v0 = src4[2 * j], v1 = src4[2 * j + 1];
            __half2 h0 = __floats2half2_rn(v0.x, v0.y);
            __half2 h1 = __floats2half2_rn(v0.z, v0.w);
            __half2 h2 = __floats2half2_rn(v1.x, v1.y);
            __half2 h3 = __floats2half2_rn(v1.z, v1.w);
            uint4 u;
            u.x = *(uint32_t*)&h0; u.y = *(uint32_t*)&h1;
            u.z = *(uint32_t*)&h2; u.w = *(uint32_t*)&h3;
            if (slot0 >= 0) ((uint4*)(g_xa[0] + (size_t)slot0 * DM))[j] = u;
            if (slot1 >= 0) ((uint4*)(g_xa[1] + (size_t)slot1 * DM))[j] = u;
        }
    } else if (bid < GATE_BLKS + PREP_BLKS) {
        // ---------------- weight transpose/convert branch ----------------
        const int p = bid - GATE_BLKS;
        const int z = p >> 11;           // 0..3
        const int r = p & 2047;
        const float* src;
        __half* dst;
        int K, N, k0, n0;
        if (z < 2) { src = w1 + (size_t)z * DM * DF; dst = g_w1t[z]; K = DM; N = DF;
                     k0 = (r & 31) * 32;  n0 = (r >> 5) * 32; }
        else       { src = w2 + (size_t)(z - 2) * DF * DM; dst = g_w2t[z - 2]; K = DF; N = DM;
                     k0 = (r & 63) * 32;  n0 = (r >> 6) * 32; }

        __shared__ float s[32][33];
        const int tx = tid & 31, ty = tid >> 5;   // 32 x 8
#pragma unroll
        for (int i = 0; i < 4; i++)
            s[ty + 8 * i][tx] = src[(size_t)(k0 + ty + 8 * i) * N + n0 + tx];
        __syncthreads();
#pragma unroll
        for (int i = 0; i < 4; i++)
            dst[(size_t)(n0 + ty + 8 * i) * K + k0 + tx] = __float2half(s[tx][ty + 8 * i]);
    } else {
        // ---------------- zero-out branch (covers output + lbl scalar) ----------------
        const int zb = bid - GATE_BLKS - PREP_BLKS;
        const int base = (zb * 256 + tid) * 16;
        if (base + 16 <= out_size) {
            float4 z4 = make_float4(0.f, 0.f, 0.f, 0.f);
            float4* o4 = (float4*)(out + base);
            o4[0] = z4; o4[1] = z4; o4[2] = z4; o4[3] = z4;
        } else {
            for (int i = base; i < out_size; i++) out[i] = 0.f;
        }
    }
}

__global__ void cleanup_kernel() {
    if (threadIdx.x < 2) g_cnt[threadIdx.x] = 0;   // restore invariant for next call
}

// ---------------- fp16 mma.sync GEMM with cp.async pipeline (R14-proven) ----------------
__device__ __forceinline__ void mma_f16(float* d, const uint32_t* a, const uint32_t* b) {
    asm volatile(
        "mma.sync.aligned.m16n8k16.row.col.f32.f16.f16.f32 "
        "{%0,%1,%2,%3}, {%4,%5,%6,%7}, {%8,%9}, {%0,%1,%2,%3};"
        : "+f"(d[0]), "+f"(d[1]), "+f"(d[2]), "+f"(d[3])
        : "r"(a[0]), "r"(a[1]), "r"(a[2]), "r"(a[3]), "r"(b[0]), "r"(b[1]));
}
__device__ __forceinline__ uint32_t smem_u32(const void* p) {
    uint32_t a;
    asm("{ .reg .u64 t; cvta.to.shared.u64 t, %1; cvt.u32.u64 %0, t; }" : "=r"(a) : "l"(p));
    return a;
}
#define CP_ASYNC16(dst, src) \
    asm volatile("cp.async.cg.shared.global [%0], [%1], 16;" :: "r"(dst), "l"(src))
#define CP_ASYNC16Z(dst, src, sz) \
    asm volatile("cp.async.cg.shared.global [%0], [%1], 16, %2;" \
                 :: "r"(dst), "l"(src), "r"(sz))
#define CP_COMMIT() asm volatile("cp.async.commit_group;" ::: "memory")
#define CP_WAIT1()  asm volatile("cp.async.wait_group 1;" ::: "memory")
#define REDV2(ptr, v0, v1) \
    asm volatile("red.global.add.v2.f32 [%0], {%1, %2};" \
                 :: "l"(ptr), "f"(v0), "f"(v1) : "memory")

// CTA tile 128x128, BK=32 (fp16), 4 warps as 2(M) x 2(N); warp tile 64x64. 128 threads.
#define BM 128
#define BN 128
#define BK 32
#define AH_STRIDE 40                       // halves per smem row (32 data + 8 pad)
#define ROW_BYTES (AH_STRIDE * 2)          // 80
#define B_OFF_H (BM * AH_STRIDE)           // 5120 halves
#define STAGE_HALVES (2 * BM * AH_STRIDE)  // 10240
#define STAGE_BYTES (STAGE_HALVES * 2)     // 20480
#define STAGES 3
#define SMEM_TOTAL (STAGES * STAGE_BYTES)  // 61440

#define LD32H(base, idx) (*(const uint32_t*)((base) + (idx)))

template <int KTOT, int KSLICE, bool IS_FFN1, int SPLITK>
__global__ void __launch_bounds__(128, 2) ffn_f16_kernel(const float* __restrict__ bias,
                                                         float* __restrict__ outp) {
    const int e     = blockIdx.z / SPLITK;
    const int split = blockIdx.z % SPLITK;
    const int n_act = g_cnt[e];
    const int m0    = blockIdx.y * BM;
    if (m0 >= n_act) return;
    const int NOUT  = IS_FFN1 ? DF : DM;
    const int n0    = blockIdx.x * BN;
    const int kbase = split * KSLICE;
    const __half* __restrict__ Ae = IS_FFN1 ? g_xa[e] : g_hh[e];
    const __half* __restrict__ Wt = IS_FFN1 ? g_w1t[e] : g_w2t[e];

    extern __shared__ __half dynsmem_h[];

    const int tid  = threadIdx.x;
    const int wid  = tid >> 5;
    const int lane = tid & 31;
    const int gid  = lane >> 2;
    const int tig  = lane & 3;
    const int wm0  = (wid >> 1) * 64;   // 0 / 64
    const int wn0  = (wid & 1) * 64;    // 0 / 64

    // A: thread t covers row m0+t; invalid rows zero-filled via cp.async src-size=0.
    const bool arow_ok = (m0 + tid) < n_act;
    const uint32_t a_sz = arow_ok ? 16u : 0u;
    const __half* aptr = Ae + (size_t)(arow_ok ? (m0 + tid) : 0) * KTOT + kbase;
    // B: thread t loads Wt row n0+t (32 halves)
    const __half* bptr = Wt + (size_t)(n0 + tid) * KTOT + kbase;

    const uint32_t as_dst = smem_u32(dynsmem_h) + (uint32_t)(tid * ROW_BYTES);
    const uint32_t bs_dst = as_dst + (uint32_t)(B_OFF_H * 2);

    const int NCHUNK = KSLICE / BK;

    auto issue = [&](int chunk) {
        if (chunk < NCHUNK) {
            const uint32_t sb = (uint32_t)((chunk % STAGES) * STAGE_BYTES);
            const __half* ap = aptr + chunk * BK;
            const __half* bp = bptr + chunk * BK;
#pragma unroll
            for (int i = 0; i < 4; i++) CP_ASYNC16Z(as_dst + sb + i * 16, ap + i * 8, a_sz);
#pragma unroll
            for (int i = 0; i < 4; i++) CP_ASYNC16(bs_dst + sb + i * 16, bp + i * 8);
        }
        CP_COMMIT();   // uniform groups: wait_group(1) always pins chunk i
    };

    float c[4][8][4];
#pragma unroll
    for (int mi = 0; mi < 4; mi++)
#pragma unroll
        for (int ni = 0; ni < 8; ni++)
#pragma unroll
            for (int q = 0; q < 4; q++) c[mi][ni][q] = 0.f;

    uint32_t a[2][4][4], b[2][8][2];

#define LOAD_FRAGS(buf, ks_)                                                  \
    do {                                                                      \
        const int kk = (ks_) * 16;                                            \
        _Pragma("unroll")                                                     \
        for (int mi = 0; mi < 4; mi++) {                                      \
            const int r = wm0 + mi * 16 + gid;                                \
            a[buf][mi][0] = LD32H(As, r * AH_STRIDE + kk + 2 * tig);          \
            a[buf][mi][1] = LD32H(As, (r + 8) * AH_STRIDE + kk + 2 * tig);    \
            a[buf][mi][2] = LD32H(As, r * AH_STRIDE + kk + 2 * tig + 8);      \
            a[buf][mi][3] = LD32H(As, (r + 8) * AH_STRIDE + kk + 2 * tig + 8);\
        }                                                                     \
        _Pragma("unroll")                                                     \
        for (int ni = 0; ni < 8; ni++) {                                      \
            const int nn = wn0 + ni * 8 + gid;                                \
            b[buf][ni][0] = LD32H(Bs, nn * AH_STRIDE + kk + 2 * tig);         \
            b[buf][ni][1] = LD32H(Bs, nn * AH_STRIDE + kk + 2 * tig + 8);     \
        }                                                                     \
    } while (0)

    issue(0);
    issue(1);

    for (int i = 0; i < NCHUNK; i++) {
        CP_WAIT1();
        __syncthreads();
        // single sync is safe: issue writes stage (i+2)%3, compute reads i%3,
        // and the overwritten stage (i-1)%3 was released by this barrier.
        issue(i + 2);

        const __half* As = dynsmem_h + (i % STAGES) * STAGE_HALVES;
        const __half* Bs = As + B_OFF_H;

        LOAD_FRAGS(0, 0);
#pragma unroll
        for (int ks = 0; ks < 2; ks++) {
            if (ks < 1) LOAD_FRAGS(1, 1);
            const int cb = ks & 1;
#pragma unroll
            for (int mi = 0; mi < 4; mi++)
#pragma unroll
                for (int ni = 0; ni < 8; ni++) mma_f16(c[mi][ni], a[cb][mi], b[cb][ni]);
        }
    }
#undef LOAD_FRAGS

    // ---------------- epilogue ----------------
    const float* bb = bias + (size_t)e * NOUT + n0;
    if (IS_FFN1) {
#pragma unroll
        for (int mi = 0; mi < 4; mi++) {
#pragma unroll
            for (int half_ = 0; half_ < 2; half_++) {
                const int r = m0 + wm0 + mi * 16 + gid + half_ * 8;
                if (r < n_act) {
                    const float sc = g_scale[e][r];          // fold scale into h
                    __half* hrow = g_hh[e] + (size_t)r * DF + n0;
#pragma unroll
                    for (int ni = 0; ni < 8; ni++) {
                        const int nn = wn0 + ni * 8 + 2 * tig;
                        float v0 = c[mi][ni][2 * half_ + 0] + bb[nn];
                        float v1 = c[mi][ni][2 * half_ + 1] + bb[nn + 1];
                        float o0 = sc * (0.5f * v0 * (1.f + erff(v0 * 0.70710678118654752f)));
                        float o1 = sc * (0.5f * v1 * (1.f + erff(v1 * 0.70710678118654752f)));
                        *(__half2*)(hrow + nn) = __floats2half2_rn(o0, o1);
                    }
                }
            }
        }
    } else {
#pragma unroll
        for (int mi = 0; mi < 4; mi++) {
#pragma unroll
            for (int half_ = 0; half_ < 2; half_++) {
                const int r = m0 + wm0 + mi * 16 + gid + half_ * 8;
                if (r < n_act) {
                    const int   tok = g_idx[e][r];
                    const float sc  = g_scale[e][r];
                    float* orow = outp + (size_t)tok * DM + n0;
#pragma unroll
                    for (int ni = 0; ni < 8; ni++) {
                        const int nn = wn0 + ni * 8 + 2 * tig;
                        // h already carries sc; bias needs sc, added by split 0 only
                        float bb0 = (split == 0) ? sc * bb[nn]     : 0.f;
                        float bb1 = (split == 0) ? sc * bb[nn + 1] : 0.f;
                        REDV2(orow + nn, c[mi][ni][2 * half_ + 0] + bb0,
                                         c[mi][ni][2 * half_ + 1] + bb1);
                    }
                }
            }
        }
    }
}

extern "C" void kernel_launch(void* const* d_in, const int* in_sizes, int n_in,
                              void* d_out, int out_size) {
    const float* x  = (const float*)d_in[0];
    const float* gw = (const float*)d_in[1];
    const float* gb = (const float*)d_in[2];
    const float* w1 = (const float*)d_in[3];
    const float* b1 = (const float*)d_in[4];
    const float* w2 = (const float*)d_in[5];
    const float* b2 = (const float*)d_in[6];
    float* out = (float*)d_out;

    cudaFuncSetAttribute(ffn_f16_kernel<DM, DM, true, 1>,
                         cudaFuncAttributeMaxDynamicSharedMemorySize, SMEM_TOTAL);
    cudaFuncSetAttribute(ffn_f16_kernel<DF, DF / 2, false, 2>,
                         cudaFuncAttributeMaxDynamicSharedMemorySize, SMEM_TOTAL);

    const int zero_blks = (out_size + 4095) / 4096;
    prologue_kernel<<<GATE_BLKS + PREP_BLKS + zero_blks, 256>>>(x, gw, gb, w1, w2,
                                                               out, out_size);
    // ffn1: active CTAs ~ 16x8x2 = 256 -> single wave at 2 CTA/SM
    ffn_f16_kernel<DM, DM, true, 1>
        <<<dim3(DF / BN, TOKENS / BM, 2), 128, SMEM_TOTAL>>>(b1, nullptr);
    // ffn2: split-K=2; active CTAs ~ 8x8x4 = 256 -> single wave at 2 CTA/SM
    ffn_f16_kernel<DF, DF / 2, false, 2>
        <<<dim3(DM / BN, TOKENS / BM, 4), 128, SMEM_TOTAL>>>(b2, out);
    cleanup_kernel<<<1, 32>>>();   // restore g_cnt==0 invariant for the next call
}

// round 17
// speedup vs baseline: 1.1585x; 1.0787x over previous
#include <cuda_runtime.h>
#include <cuda_fp16.h>
#include <math.h>
#include <stdint.h>

#define TOKENS 8192
#define DM 1024
#define DF 2048
#define NE 8

// ---------------- scratch (device globals: allocation-free, graph-safe) -------------
// g_cnt/g_done statically zero-init; ffn2's last block restores them each call.
__device__ int    g_cnt[2];
__device__ int    g_done;
__device__ int    g_idx[2][TOKENS];
__device__ float  g_scale[2][TOKENS];
__device__ __half g_xa[2][(size_t)TOKENS * DM];   // compacted fp16 x rows
__device__ __half g_hh[2][(size_t)TOKENS * DF];   // fp16 h rows (scale folded)
__device__ __half g_w1t[2][(size_t)DM * DF];      // w1 transposed: [n=2048][k=1024]
__device__ __half g_w2t[2][(size_t)DF * DM];      // w2 transposed: [n=1024][k=2048]

#define GATE_BLKS 1024
#define PREP_BLKS 8192   // 4 mats x 2048 tight 32x32 tiles

// One fused prologue: gate+compact+fp16-scatter | weight transpose/convert | zero out.
__global__ __launch_bounds__(256) void prologue_kernel(const float* __restrict__ x,
                                                       const float* __restrict__ gw,
                                                       const float* __restrict__ gb,
                                                       const float* __restrict__ w1,
                                                       const float* __restrict__ w2,
                                                       float* __restrict__ out,
                                                       int out_size) {
    const int bid = blockIdx.x;
    const int tid = threadIdx.x;

    if (bid < GATE_BLKS) {
        // ---------------- gate branch (8 warps -> 8 tokens) ----------------
        __shared__ float sgwT[NE][DM];
        for (int i = tid; i < DM * NE; i += 256) {
            int d = i >> 3, e = i & 7;   // gw is [d][e] row-major
            sgwT[e][d] = gw[i];
        }
        __syncthreads();

        const int t    = bid * 8 + (tid >> 5);
        const int lane = tid & 31;

        const float* xr = x + (size_t)t * DM;
        float acc[NE];
#pragma unroll
        for (int e = 0; e < NE; e++) acc[e] = 0.f;
        for (int d = lane; d < DM; d += 32) {
            const float xv = xr[d];
#pragma unroll
            for (int e = 0; e < NE; e++) acc[e] += xv * sgwT[e][d];
        }
#pragma unroll
        for (int e = 0; e < NE; e++)
#pragma unroll
            for (int o = 16; o > 0; o >>= 1) acc[e] += __shfl_xor_sync(0xffffffffu, acc[e], o);

        int s0v = -1, s1v = -1;
        if (lane == 0) {
            float p[NE];
            float mx = -1e30f;
#pragma unroll
            for (int e = 0; e < NE; e++) { p[e] = acc[e] + gb[e]; mx = fmaxf(mx, p[e]); }
            float s = 0.f;
#pragma unroll
            for (int e = 0; e < NE; e++) { p[e] = expf(p[e] - mx); s += p[e]; }
            float inv = 1.f / s;
#pragma unroll
            for (int e = 0; e < NE; e++) p[e] *= inv;
            int i1 = 0;
#pragma unroll
            for (int e = 1; e < NE; e++) if (p[e] > p[i1]) i1 = e;
            int i2 = (i1 == 0) ? 1 : 0;
#pragma unroll
            for (int e = 0; e < NE; e++) if (e != i1 && p[e] > p[i2]) i2 = e;
            if (i1 == 0) { s0v = atomicAdd(&g_cnt[0], 1); g_idx[0][s0v] = t; g_scale[0][s0v] = p[0]; }
            if (i2 == 1) { s1v = atomicAdd(&g_cnt[1], 1); g_idx[1][s1v] = t; g_scale[1][s1v] = p[1]; }
        }
        const int slot0 = __shfl_sync(0xffffffffu, s0v, 0);
        const int slot1 = __shfl_sync(0xffffffffu, s1v, 0);
        if (slot0 < 0 && slot1 < 0) return;

        const float4* src4 = (const float4*)xr;
        for (int j = lane; j < DM / 8; j += 32) {
            float4 v0 = src4[2 * j], v1 = src4[2 * j + 1];
            __half2 h0 = __floats2half2_rn(v0.x, v0.y);
            __half2 h1 = __floats2half2_rn(v0.z, v0.w);
            __half2 h2 = __floats2half2_rn(v1.x, v1.y);
            __half2 h3 = __floats2half2_rn(v1.z, v1.w);
            uint4 u;
            u.x = *(uint32_t*)&h0; u.y = *(uint32_t*)&h1;
            u.z = *(uint32_t*)&h2; u.w = *(uint32_t*)&h3;
            if (slot0 >= 0) ((uint4*)(g_xa[0] + (size_t)slot0 * DM))[j] = u;
            if (slot1 >= 0) ((uint4*)(g_xa[1] + (size_t)slot1 * DM))[j] = u;
        }
    } else if (bid < GATE_BLKS + PREP_BLKS) {
        // ---------------- weight transpose/convert branch ----------------
        const int p = bid - GATE_BLKS;
        const int z = p >> 11;           // 0..3
        const int r = p & 2047;
        const float* src;
        __half* dst;
        int K, N, k0, n0;
        if (z < 2) { src = w1 + (size_t)z * DM * DF; dst = g_w1t[z]; K = DM; N = DF;
                     k0 = (r & 31) * 32;  n0 = (r >> 5) * 32; }
        else       { src = w2 + (size_t)(z - 2) * DF * DM; dst = g_w2t[z - 2]; K = DF; N = DM;
                     k0 = (r & 63) * 32;  n0 = (r >> 6) * 32; }

        __shared__ float s[32][33];
        const int tx = tid & 31, ty = tid >> 5;   // 32 x 8
#pragma unroll
        for (int i = 0; i < 4; i++)
            s[ty + 8 * i][tx] = src[(size_t)(k0 + ty + 8 * i) * N + n0 + tx];
        __syncthreads();
#pragma unroll
        for (int i = 0; i < 4; i++)
            dst[(size_t)(n0 + ty + 8 * i) * K + k0 + tx] = __float2half(s[tx][ty + 8 * i]);
    } else {
        // ---------------- zero-out branch (covers output + lbl scalar) ----------------
        const int zb = bid - GATE_BLKS - PREP_BLKS;
        const int base = (zb * 256 + tid) * 16;
        if (base + 16 <= out_size) {
            float4 z4 = make_float4(0.f, 0.f, 0.f, 0.f);
            float4* o4 = (float4*)(out + base);
            o4[0] = z4; o4[1] = z4; o4[2] = z4; o4[3] = z4;
        } else {
            for (int i = base; i < out_size; i++) out[i] = 0.f;
        }
    }
}

// ---------------- fp16 mma.sync GEMM: cp.async pipeline + ldmatrix ----------------
__device__ __forceinline__ void mma_f16(float* d, const uint32_t* a, const uint32_t* b) {
    asm volatile(
        "mma.sync.aligned.m16n8k16.row.col.f32.f16.f16.f32 "
        "{%0,%1,%2,%3}, {%4,%5,%6,%7}, {%8,%9}, {%0,%1,%2,%3};"
        : "+f"(d[0]), "+f"(d[1]), "+f"(d[2]), "+f"(d[3])
        : "r"(a[0]), "r"(a[1]), "r"(a[2]), "r"(a[3]), "r"(b[0]), "r"(b[1]));
}
__device__ __forceinline__ uint32_t smem_u32(const void* p) {
    uint32_t a;
    asm("{ .reg .u64 t; cvta.to.shared.u64 t, %1; cvt.u32.u64 %0, t; }" : "=r"(a) : "l"(p));
    return a;
}
#define LDM4(r0, r1, r2, r3, addr) \
    asm volatile("ldmatrix.sync.aligned.m8n8.x4.shared.b16 {%0,%1,%2,%3}, [%4];" \
                 : "=r"(r0), "=r"(r1), "=r"(r2), "=r"(r3) : "r"(addr))
#define CP_ASYNC16(dst, src) \
    asm volatile("cp.async.cg.shared.global [%0], [%1], 16;" :: "r"(dst), "l"(src))
#define CP_ASYNC16Z(dst, src, sz) \
    asm volatile("cp.async.cg.shared.global [%0], [%1], 16, %2;" \
                 :: "r"(dst), "l"(src), "r"(sz))
#define CP_COMMIT() asm volatile("cp.async.commit_group;" ::: "memory")
#define CP_WAIT1()  asm volatile("cp.async.wait_group 1;" ::: "memory")
#define REDV2(ptr, v0, v1) \
    asm volatile("red.global.add.v2.f32 [%0], {%1, %2};" \
                 :: "l"(ptr), "f"(v0), "f"(v1) : "memory")

// CTA tile 128x128, BK=32 (fp16), 4 warps as 2(M) x 2(N); warp tile 64x64. 128 threads.
#define BM 128
#define BN 128
#define BK 32
#define AH_STRIDE 40                       // halves per smem row (32 data + 8 pad)
#define ROW_BYTES (AH_STRIDE * 2)          // 80
#define B_OFF_H (BM * AH_STRIDE)           // 5120 halves
#define STAGE_HALVES (2 * BM * AH_STRIDE)  // 10240
#define STAGE_BYTES (STAGE_HALVES * 2)     // 20480
#define STAGES 3
#define SMEM_TOTAL (STAGES * STAGE_BYTES)  // 61440

template <int KTOT, int KSLICE, bool IS_FFN1, int SPLITK>
__global__ void __launch_bounds__(128, 2) ffn_f16_kernel(const float* __restrict__ bias,
                                                         float* __restrict__ outp) {
    const int e     = blockIdx.z / SPLITK;
    const int split = blockIdx.z % SPLITK;
    const int n_act = g_cnt[e];
    const int m0    = blockIdx.y * BM;

    const int tid  = threadIdx.x;
    const int wid  = tid >> 5;
    const int lane = tid & 31;

    if (m0 < n_act) {
        const int NOUT  = IS_FFN1 ? DF : DM;
        const int n0    = blockIdx.x * BN;
        const int kbase = split * KSLICE;
        const __half* __restrict__ Ae = IS_FFN1 ? g_xa[e] : g_hh[e];
        const __half* __restrict__ Wt = IS_FFN1 ? g_w1t[e] : g_w2t[e];

        extern __shared__ __half dynsmem_h[];

        const int gid = lane >> 2;
        const int tig = lane & 3;
        const int wm0 = (wid >> 1) * 64;   // 0 / 64
        const int wn0 = (wid & 1) * 64;    // 0 / 64

        // A: thread t covers row m0+t; invalid rows zero-filled via cp.async src-size=0.
        const bool arow_ok = (m0 + tid) < n_act;
        const uint32_t a_sz = arow_ok ? 16u : 0u;
        const __half* aptr = Ae + (size_t)(arow_ok ? (m0 + tid) : 0) * KTOT + kbase;
        const __half* bptr = Wt + (size_t)(n0 + tid) * KTOT + kbase;

        const uint32_t smem32 = smem_u32(dynsmem_h);
        const uint32_t as_dst = smem32 + (uint32_t)(tid * ROW_BYTES);
        const uint32_t bs_dst = as_dst + (uint32_t)(B_OFF_H * 2);

        // ldmatrix per-lane row offsets (halves)
        uint32_t aoff[4], boff[4];
#pragma unroll
        for (int mi = 0; mi < 4; mi++)
            aoff[mi] = (uint32_t)(((wm0 + mi * 16 + (lane & 7) + ((lane >> 3) & 1) * 8)
                                   * AH_STRIDE) + (lane >> 4) * 8);
#pragma unroll
        for (int nj = 0; nj < 4; nj++)
            boff[nj] = (uint32_t)(((wn0 + nj * 16 + ((lane >> 4) & 1) * 8 + (lane & 7))
                                   * AH_STRIDE) + ((lane >> 3) & 1) * 8);

        const int NCHUNK = KSLICE / BK;

        auto issue = [&](int chunk) {
            if (chunk < NCHUNK) {
                const uint32_t sb = (uint32_t)((chunk % STAGES) * STAGE_BYTES);
                const __half* ap = aptr + chunk * BK;
                const __half* bp = bptr + chunk * BK;
#pragma unroll
                for (int i = 0; i < 4; i++) CP_ASYNC16Z(as_dst + sb + i * 16, ap + i * 8, a_sz);
#pragma unroll
                for (int i = 0; i < 4; i++) CP_ASYNC16(bs_dst + sb + i * 16, bp + i * 8);
            }
            CP_COMMIT();   // uniform groups: wait_group(1) always pins chunk i
        };

        float c[4][8][4];
#pragma unroll
        for (int mi = 0; mi < 4; mi++)
#pragma unroll
            for (int ni = 0; ni < 8; ni++)
#pragma unroll
                for (int q = 0; q < 4; q++) c[mi][ni][q] = 0.f;

        uint32_t a[2][4][4], b[2][8][2];

#define LOAD_FRAGS(buf, ks_)                                                   \
        do {                                                                   \
            const uint32_t kb = (uint32_t)((ks_) * 32);  /* 16 halves * 2B */  \
            _Pragma("unroll")                                                  \
            for (int mi = 0; mi < 4; mi++)                                     \
                LDM4(a[buf][mi][0], a[buf][mi][1], a[buf][mi][2], a[buf][mi][3],\
                     As32 + aoff[mi] * 2 + kb);                                \
            _Pragma("unroll")                                                  \
            for (int nj = 0; nj < 4; nj++)                                     \
                LDM4(b[buf][2 * nj][0], b[buf][2 * nj][1],                     \
                     b[buf][2 * nj + 1][0], b[buf][2 * nj + 1][1],             \
                     Bs32 + boff[nj] * 2 + kb);                                \
        } while (0)

        issue(0);
        issue(1);

        for (int i = 0; i < NCHUNK; i++) {
            CP_WAIT1();
            __syncthreads();
            // single sync safe: issue writes stage (i+2)%3, ldmatrix reads i%3,
            // and the overwritten stage (i-1)%3 was released at this barrier.
            issue(i + 2);

            const uint32_t As32 = smem32 + (uint32_t)((i % STAGES) * STAGE_BYTES);
            const uint32_t Bs32 = As32 + (uint32_t)(B_OFF_H * 2);

            LOAD_FRAGS(0, 0);
#pragma unroll
            for (int ks = 0; ks < 2; ks++) {
                if (ks < 1) LOAD_FRAGS(1, 1);
                const int cb = ks & 1;
#pragma unroll
                for (int mi = 0; mi < 4; mi++)
#pragma unroll
                    for (int ni = 0; ni < 8; ni++) mma_f16(c[mi][ni], a[cb][mi], b[cb][ni]);
            }
        }
#undef LOAD_FRAGS

        // ---------------- epilogue ----------------
        const float* bb = bias + (size_t)e * NOUT + n0;
        if (IS_FFN1) {
#pragma unroll
            for (int mi = 0; mi < 4; mi++) {
#pragma unroll
                for (int half_ = 0; half_ < 2; half_++) {
                    const int r = m0 + wm0 + mi * 16 + gid + half_ * 8;
                    if (r < n_act) {
                        const float sc = g_scale[e][r];      // fold scale into h
                        __half* hrow = g_hh[e] + (size_t)r * DF + n0;
#pragma unroll
                        for (int ni = 0; ni < 8; ni++) {
                            const int nn = wn0 + ni * 8 + 2 * tig;
                            float v0 = c[mi][ni][2 * half_ + 0] + bb[nn];
                            float v1 = c[mi][ni][2 * half_ + 1] + bb[nn + 1];
                            float o0 = sc * (0.5f * v0 * (1.f + erff(v0 * 0.70710678118654752f)));
                            float o1 = sc * (0.5f * v1 * (1.f + erff(v1 * 0.70710678118654752f)));
                            *(__half2*)(hrow + nn) = __floats2half2_rn(o0, o1);
                        }
                    }
                }
            }
        } else {
#pragma unroll
            for (int mi = 0; mi < 4; mi++) {
#pragma unroll
                for (int half_ = 0; half_ < 2; half_++) {
                    const int r = m0 + wm0 + mi * 16 + gid + half_ * 8;
                    if (r < n_act) {
                        const int   tok = g_idx[e][r];
                        const float sc  = g_scale[e][r];
                        float* orow = outp + (size_t)tok * DM + n0;
#pragma unroll
                        for (int ni = 0; ni < 8; ni++) {
                            const int nn = wn0 + ni * 8 + 2 * tig;
                            // h already carries sc; bias needs sc, added by split 0 only
                            float bb0 = (split == 0) ? sc * bb[nn]     : 0.f;
                            float bb1 = (split == 0) ? sc * bb[nn + 1] : 0.f;
                            REDV2(orow + nn, c[mi][ni][2 * half_ + 0] + bb0,
                                             c[mi][ni][2 * half_ + 1] + bb1);
                        }
                    }
                }
            }
        }
    }

    // ---------------- fused cleanup (ffn2 only): last block resets counters ----------
    if (!IS_FFN1) {
        __syncthreads();   // whole block done with g_cnt/g_idx/g_scale reads
        if (tid == 0) {
            const int total = gridDim.x * gridDim.y * gridDim.z;
            if (atomicAdd(&g_done, 1) == total - 1) {
                g_cnt[0] = 0; g_cnt[1] = 0; g_done = 0;   // invariant for next call
            }
        }
    }
}

extern "C" void kernel_launch(void* const* d_in, const int* in_sizes, int n_in,
                              void* d_out, int out_size) {
    const float* x  = (const float*)d_in[0];
    const float* gw = (const float*)d_in[1];
    const float* gb = (const float*)d_in[2];
    const float* w1 = (const float*)d_in[3];
    const float* b1 = (const float*)d_in[4];
    const float* w2 = (const float*)d_in[5];
    const float* b2 = (const float*)d_in[6];
    float* out = (float*)d_out;

    cudaFuncSetAttribute(ffn_f16_kernel<DM, DM, true, 1>,
                         cudaFuncAttributeMaxDynamicSharedMemorySize, SMEM_TOTAL);
    cudaFuncSetAttribute(ffn_f16_kernel<DF, DF / 2, false, 2>,
                         cudaFuncAttributeMaxDynamicSharedMemorySize, SMEM_TOTAL);

    const int zero_blks = (out_size + 4095) / 4096;
    prologue_kernel<<<GATE_BLKS + PREP_BLKS + zero_blks, 256>>>(x, gw, gb, w1, w2,
                                                               out, out_size);
    // ffn1: active CTAs ~ 16x8x2 = 256 -> single wave at 2 CTA/SM
    ffn_f16_kernel<DM, DM, true, 1>
        <<<dim3(DF / BN, TOKENS / BM, 2), 128, SMEM_TOTAL>>>(b1, nullptr);
    // ffn2: split-K=2; active CTAs ~ 8x8x4 = 256 -> single wave at 2 CTA/SM
    ffn_f16_kernel<DF, DF / 2, false, 2>
        <<<dim3(DM / BN, TOKENS / BM, 4), 128, SMEM_TOTAL>>>(b2, out);
}